// round 5
// baseline (speedup 1.0000x reference)
#include <cuda_runtime.h>

// out[b,c,h,w] = (1/256) * sum_{p,o in 0..8} inp[b, p*9+o, h, w] * sec[b, c, h+p-4, w+o-4]
// B=8, C=256, H=W=128.

#define MD 4
#define NTAPS 81
#define HH 128
#define WW 128
#define CC 256

#define TH 8
#define TW 32
#define CB 32                    // channels staged per iteration
#define NCB (CC/CB)              // 8
#define NCH 8                    // channels per thread
#define NT 512                   // 256 "compute lanes" x 2 p-halves

#define SSTR 44                  // sec row stride (floats)
#define SPLANE (16*SSTR)         // 704 floats / channel
#define WSM_FLOATS (NTAPS*TH*TW) // 20736
#define SSM_FLOATS (CB*SPLANE)   // 22528
#define RED_U64 (16*256)         // 16 u64 per compute-lane
#define SMEM_BYTES ((WSM_FLOATS+SSM_FLOATS)*4 + RED_U64*8)   // 205824 B

typedef unsigned long long u64;

__device__ __forceinline__ u64 pack2(float a, float b) {
    u64 r; asm("mov.b64 %0,{%1,%2};" : "=l"(r) : "f"(a), "f"(b)); return r;
}
__device__ __forceinline__ void ffma2(u64& acc, u64 a, u64 b) {
    asm("fma.rn.f32x2 %0, %1, %2, %0;" : "+l"(acc) : "l"(a), "l"(b));
}
__device__ __forceinline__ void fadd2(u64& a, u64 b) {
    asm("add.rn.f32x2 %0, %0, %1;" : "+l"(a) : "l"(b));
}
__device__ __forceinline__ u64 fmul2(u64 a, u64 b) {
    u64 r; asm("mul.rn.f32x2 %0, %1, %2;" : "=l"(r) : "l"(a), "l"(b)); return r;
}
__device__ __forceinline__ void lds_v2u64(u64& x, u64& y, unsigned addr) {
    asm volatile("ld.shared.v2.b64 {%0,%1},[%2];" : "=l"(x), "=l"(y) : "r"(addr));
}
__device__ __forceinline__ float lo32(u64 a) { return __uint_as_float((unsigned)(a & 0xffffffffull)); }
__device__ __forceinline__ float hi32(u64 a) { return __uint_as_float((unsigned)(a >> 32)); }

__global__ void __launch_bounds__(NT, 1)
corr_transpose_kernel(const float* __restrict__ inp,
                      const float* __restrict__ sec,
                      float* __restrict__ out)
{
    extern __shared__ float smem[];
    float* wsm = smem;                                  // [81][8][32]
    float* ssm = smem + WSM_FLOATS;                     // [32 ch][16 rows][44]
    u64*   red = (u64*)(smem + WSM_FLOATS + SSM_FLOATS);// [16][256]

    const int tid = threadIdx.x;
    const int tx  = tid & 7;            // pixel col group (4 px)
    const int ty  = (tid >> 3) & 7;     // pixel row
    const int cs  = (tid >> 6) & 3;     // channel subgroup (8 ch each)
    const int ph  = tid >> 8;           // p-parity half: 0 -> even p, 1 -> odd p
    const int t256 = tid & 255;         // compute-lane id
    const int gx  = blockIdx.x * TW;
    const int gy  = blockIdx.y * TH;
    const int b   = blockIdx.z;

    // ---- stage all 81 weight planes for this 8x32 tile (once) ----
    for (int idx = tid; idx < NTAPS * TH * (TW / 4); idx += NT) {
        int col4 = idx & 7;
        int row  = (idx >> 3) & 7;
        int d    = idx >> 6;
        float4 v = *(const float4*)(inp + (((size_t)(b * NTAPS + d) * HH + gy + row) * WW + gx + col4 * 4));
        *(float4*)(wsm + (d * TH + row) * TW + col4 * 4) = v;
    }

    const unsigned wsm_addr = (unsigned)__cvta_generic_to_shared(wsm + ty * TW + 4 * tx);
    const float*   sbase    = ssm + (cs * NCH) * SPLANE + ty * SSTR + 4 * tx;
    const u64 scale2 = pack2(1.0f / (float)CC, 1.0f / (float)CC);
    const int srow_t = tid & 15;        // staging row 0..15
    const int sch    = (tid >> 4) & 31; // staged channel 0..31

    const int np = 5 - ph;              // ph=0: p=0,2,4,6,8 ; ph=1: p=1,3,5,7

    for (int cb = 0; cb < NCB; cb++) {
        __syncthreads();   // previous ssm/red consumers done

        // ---- stage 32 channels of sec with halo (each thread: one (ch,row), 10 float4) ----
        {
            const float* gsec = sec + ((size_t)(b * CC + cb * CB + sch) * HH) * WW;
            float* plane = ssm + sch * SPLANE;
            int r = gy + srow_t - MD;
            #pragma unroll
            for (int c4 = 0; c4 < 10; c4++) {
                int c = gx - MD + 4 * c4;
                float4 v = make_float4(0.f, 0.f, 0.f, 0.f);
                if ((unsigned)r < HH) {
                    if (c >= 0 && c <= WW - 4) {
                        v = *(const float4*)(gsec + (size_t)r * WW + c);
                    } else {
                        const float* gr = gsec + (size_t)r * WW;
                        if ((unsigned)(c + 0) < WW) v.x = gr[c + 0];
                        if ((unsigned)(c + 1) < WW) v.y = gr[c + 1];
                        if ((unsigned)(c + 2) < WW) v.z = gr[c + 2];
                        if ((unsigned)(c + 3) < WW) v.w = gr[c + 3];
                    }
                }
                *(float4*)(plane + srow_t * SSTR + 4 * c4) = v;
            }
        }
        __syncthreads();

        // ---- compute: 8 channels x 4 px over this half's p values ----
        u64 acc[NCH][2];
        #pragma unroll
        for (int j = 0; j < NCH; j++) { acc[j][0] = 0ull; acc[j][1] = 0ull; }

        #pragma unroll 1
        for (int pp = 0; pp < np; pp++) {
            const int p = 2 * pp + ph;
            u64 wp[9][2];
            #pragma unroll
            for (int o = 0; o < 9; o++)
                lds_v2u64(wp[o][0], wp[o][1], wsm_addr + (unsigned)(((p * 9 + o) * TH * TW) << 2));

            #pragma unroll
            for (int j = 0; j < NCH; j++) {
                const float4* srow = (const float4*)(sbase + j * SPLANE + p * SSTR);
                float4 v0 = srow[0];
                float4 v1 = srow[1];
                float4 v2 = srow[2];
                u64 A0 = pack2(v0.x, v0.y), A1 = pack2(v0.z, v0.w);
                u64 A2 = pack2(v1.x, v1.y), A3 = pack2(v1.z, v1.w);
                u64 A4 = pack2(v2.x, v2.y), A5 = pack2(v2.z, v2.w);
                u64 M0 = pack2(v0.y, v0.z), M1 = pack2(v0.w, v1.x);
                u64 M2 = pack2(v1.y, v1.z), M3 = pack2(v1.w, v2.x);
                u64 M4 = pack2(v2.y, v2.z);
                u64 A[6] = {A0, A1, A2, A3, A4, A5};
                u64 M[5] = {M0, M1, M2, M3, M4};
                #pragma unroll
                for (int o = 0; o < 9; o++) {
                    u64 s0, s1;
                    if ((o & 1) == 0) { s0 = A[o >> 1]; s1 = A[(o >> 1) + 1]; }
                    else              { s0 = M[o >> 1]; s1 = M[(o >> 1) + 1]; }
                    ffma2(acc[j][0], wp[o][0], s0);
                    ffma2(acc[j][1], wp[o][1], s1);
                }
            }
        }

        // ---- ph=1 publishes partials ----
        if (ph == 1) {
            #pragma unroll
            for (int j = 0; j < NCH; j++) {
                red[(2 * j + 0) * 256 + t256] = acc[j][0];
                red[(2 * j + 1) * 256 + t256] = acc[j][1];
            }
        }
        __syncthreads();

        // ---- ph=0 merges, scales, stores 8 channels x 4 px ----
        if (ph == 0) {
            #pragma unroll
            for (int j = 0; j < NCH; j++) {
                fadd2(acc[j][0], red[(2 * j + 0) * 256 + t256]);
                fadd2(acc[j][1], red[(2 * j + 1) * 256 + t256]);
                u64 r0 = fmul2(acc[j][0], scale2);
                u64 r1 = fmul2(acc[j][1], scale2);
                int c = cb * CB + cs * NCH + j;
                float4 o4 = make_float4(lo32(r0), hi32(r0), lo32(r1), hi32(r1));
                *(float4*)(out + (((size_t)(b * CC + c) * HH + gy + ty) * WW + gx + 4 * tx)) = o4;
            }
        }
    }
}

extern "C" void kernel_launch(void* const* d_in, const int* in_sizes, int n_in,
                              void* d_out, int out_size)
{
    const float* inp = (const float*)d_in[0];   // [B, 81, 128, 128]
    const float* sec = (const float*)d_in[1];   // [B, 256, 128, 128]
    float* out = (float*)d_out;                 // [B, 256, 128, 128]

    const int B = in_sizes[0] / (NTAPS * HH * WW);

    cudaFuncSetAttribute(corr_transpose_kernel,
                         cudaFuncAttributeMaxDynamicSharedMemorySize, SMEM_BYTES);

    dim3 grid(WW / TW, HH / TH, B);   // (4, 16, 8)
    corr_transpose_kernel<<<grid, NT, SMEM_BYTES>>>(inp, sec, out);
}

// round 6
// speedup vs baseline: 1.2401x; 1.2401x over previous
#include <cuda_runtime.h>

// out[b,c,h,w] = (1/256) * sum_{p,o in 0..8} inp[b, p*9+o, h, w] * sec[b, c, h+p-4, w+o-4]
// B=8, C=256, H=W=128.

#define MD 4
#define NTAPS 81
#define HH 128
#define WW 128
#define CC 256

#define TH 8
#define TW 32
#define CB 32                    // channels staged per iteration
#define NCB (CC/CB)              // 8
#define NCH 4                    // channels per thread
#define NPX 8                    // pixels per thread
#define NT 256

#define WSTR 36                  // weight plane row stride (144B -> +4 bank rot per row)
#define WPLANE (TH*WSTR)         // 288 floats
#define WSM_FLOATS (NTAPS*WPLANE)// 23328
#define SSTR 44                  // sec row stride (176B -> +12 bank rot per row)
#define SPLANE (16*SSTR)         // 704 floats / channel
#define SSM_FLOATS (CB*SPLANE)   // 22528
#define SMEM_BYTES ((WSM_FLOATS+SSM_FLOATS)*4)  // 183424 B

typedef unsigned long long u64;

__device__ __forceinline__ u64 pack2(float a, float b) {
    u64 r; asm("mov.b64 %0,{%1,%2};" : "=l"(r) : "f"(a), "f"(b)); return r;
}
__device__ __forceinline__ void ffma2(u64& acc, u64 a, u64 b) {
    asm("fma.rn.f32x2 %0, %1, %2, %0;" : "+l"(acc) : "l"(a), "l"(b));
}
__device__ __forceinline__ u64 fmul2(u64 a, u64 b) {
    u64 r; asm("mul.rn.f32x2 %0, %1, %2;" : "=l"(r) : "l"(a), "l"(b)); return r;
}
__device__ __forceinline__ void lds_v2u64(u64& x, u64& y, unsigned addr) {
    asm volatile("ld.shared.v2.b64 {%0,%1},[%2];" : "=l"(x), "=l"(y) : "r"(addr));
}
__device__ __forceinline__ void lds_v4f(float& a, float& b, float& c, float& d, unsigned addr) {
    asm volatile("ld.shared.v4.f32 {%0,%1,%2,%3},[%4];" : "=f"(a), "=f"(b), "=f"(c), "=f"(d) : "r"(addr));
}
__device__ __forceinline__ float lo32(u64 a) { return __uint_as_float((unsigned)(a & 0xffffffffull)); }
__device__ __forceinline__ float hi32(u64 a) { return __uint_as_float((unsigned)(a >> 32)); }

__global__ void __launch_bounds__(NT, 1)
corr_transpose_kernel(const float* __restrict__ inp,
                      const float* __restrict__ sec,
                      float* __restrict__ out)
{
    extern __shared__ float smem[];
    float* wsm = smem;                  // [81][8][36]
    float* ssm = smem + WSM_FLOATS;     // [32 ch][16 rows][44]

    const int tid = threadIdx.x;
    const int tx  = tid & 3;            // pixel col group (8 px each)
    const int ty  = (tid >> 2) & 7;     // pixel row
    const int cs  = tid >> 5;           // channel subgroup 0..7 (4 ch each)
    const int gx  = blockIdx.x * TW;
    const int gy  = blockIdx.y * TH;
    const int b   = blockIdx.z;

    // ---- stage all 81 weight planes (row stride padded to 36) ----
    for (int idx = tid; idx < NTAPS * TH * (TW / 4); idx += NT) {
        int col4 = idx & 7;
        int row  = (idx >> 3) & 7;
        int d    = idx >> 6;
        float4 v = *(const float4*)(inp + (((size_t)(b * NTAPS + d) * HH + gy + row) * WW + gx + col4 * 4));
        *(float4*)(wsm + d * WPLANE + row * WSTR + col4 * 4) = v;
    }

    const unsigned smbase   = (unsigned)__cvta_generic_to_shared(smem);
    const unsigned waddr    = smbase + (unsigned)((ty * WSTR + 8 * tx) * 4);
    const unsigned saddr0   = smbase + (unsigned)((WSM_FLOATS + (cs * NCH) * SPLANE + ty * SSTR + 8 * tx) * 4);
    const u64 scale2 = pack2(1.0f / (float)CC, 1.0f / (float)CC);

    for (int cb = 0; cb < NCB; cb++) {
        __syncthreads();   // previous compute done before restaging

        // ---- stage 32 channels of sec with halo: 2 (ch,row) slots per thread ----
        #pragma unroll
        for (int s = 0; s < 2; s++) {
            int slot = tid + s * NT;
            int srow_t = slot & 15;
            int sch    = slot >> 4;
            const float* gsec = sec + ((size_t)(b * CC + cb * CB + sch) * HH) * WW;
            float* plane = ssm + sch * SPLANE;
            int r = gy + srow_t - MD;
            #pragma unroll
            for (int c4 = 0; c4 < 10; c4++) {
                int c = gx - MD + 4 * c4;
                float4 v = make_float4(0.f, 0.f, 0.f, 0.f);
                if ((unsigned)r < HH) {
                    if (c >= 0 && c <= WW - 4) {
                        v = *(const float4*)(gsec + (size_t)r * WW + c);
                    } else {
                        const float* gr = gsec + (size_t)r * WW;
                        if ((unsigned)(c + 0) < WW) v.x = gr[c + 0];
                        if ((unsigned)(c + 1) < WW) v.y = gr[c + 1];
                        if ((unsigned)(c + 2) < WW) v.z = gr[c + 2];
                        if ((unsigned)(c + 3) < WW) v.w = gr[c + 3];
                    }
                }
                *(float4*)(plane + srow_t * SSTR + 4 * c4) = v;
            }
        }
        __syncthreads();

        // ---- compute: 4 channels x 8 px per thread ----
        u64 acc[NCH][4];
        #pragma unroll
        for (int j = 0; j < NCH; j++)
            #pragma unroll
            for (int k = 0; k < 4; k++) acc[j][k] = 0ull;

        #pragma unroll 1
        for (int p = 0; p < 9; p++) {
            // weights: 9 taps x 4 pixel-pairs (aligned)
            u64 wp[9][4];
            #pragma unroll
            for (int o = 0; o < 9; o++) {
                unsigned a = waddr + (unsigned)(((p * 9 + o) * WPLANE) * 4);
                lds_v2u64(wp[o][0], wp[o][1], a);
                lds_v2u64(wp[o][2], wp[o][3], a + 16u);
            }

            #pragma unroll
            for (int j = 0; j < NCH; j++) {
                unsigned sa = saddr0 + (unsigned)((j * SPLANE + p * SSTR) * 4);
                // window: 16 floats = px 8tx-?.. s[0..15] covering 8 px + 8 halo
                float f0,f1,f2,f3,f4,f5,f6,f7,f8,f9,f10,f11,f12,f13,f14,f15;
                lds_v4f(f0, f1, f2, f3,  sa);
                lds_v4f(f4, f5, f6, f7,  sa + 16u);
                lds_v4f(f8, f9, f10,f11, sa + 32u);
                lds_v4f(f12,f13,f14,f15, sa + 48u);
                u64 A[8] = { pack2(f0,f1),  pack2(f2,f3),  pack2(f4,f5),  pack2(f6,f7),
                             pack2(f8,f9),  pack2(f10,f11),pack2(f12,f13),pack2(f14,f15) };
                u64 M[7] = { pack2(f1,f2),  pack2(f3,f4),  pack2(f5,f6),  pack2(f7,f8),
                             pack2(f9,f10), pack2(f11,f12),pack2(f13,f14) };
                #pragma unroll
                for (int o = 0; o < 9; o++) {
                    if ((o & 1) == 0) {
                        #pragma unroll
                        for (int k = 0; k < 4; k++)
                            ffma2(acc[j][k], wp[o][k], A[(o >> 1) + k]);
                    } else {
                        #pragma unroll
                        for (int k = 0; k < 4; k++)
                            ffma2(acc[j][k], wp[o][k], M[(o >> 1) + k]);
                    }
                }
            }
        }

        // ---- store 4 channels x 8 px ----
        #pragma unroll
        for (int j = 0; j < NCH; j++) {
            int c = cb * CB + cs * NCH + j;
            float* optr = out + (((size_t)(b * CC + c) * HH + gy + ty) * WW + gx + 8 * tx);
            u64 r0 = fmul2(acc[j][0], scale2);
            u64 r1 = fmul2(acc[j][1], scale2);
            u64 r2 = fmul2(acc[j][2], scale2);
            u64 r3 = fmul2(acc[j][3], scale2);
            *(float4*)(optr)     = make_float4(lo32(r0), hi32(r0), lo32(r1), hi32(r1));
            *(float4*)(optr + 4) = make_float4(lo32(r2), hi32(r2), lo32(r3), hi32(r3));
        }
    }
}

extern "C" void kernel_launch(void* const* d_in, const int* in_sizes, int n_in,
                              void* d_out, int out_size)
{
    const float* inp = (const float*)d_in[0];   // [B, 81, 128, 128]
    const float* sec = (const float*)d_in[1];   // [B, 256, 128, 128]
    float* out = (float*)d_out;                 // [B, 256, 128, 128]

    const int B = in_sizes[0] / (NTAPS * HH * WW);

    cudaFuncSetAttribute(corr_transpose_kernel,
                         cudaFuncAttributeMaxDynamicSharedMemorySize, SMEM_BYTES);

    dim3 grid(WW / TW, HH / TH, B);   // (4, 16, 8)
    corr_transpose_kernel<<<grid, NT, SMEM_BYTES>>>(inp, sec, out);
}